// round 11
// baseline (speedup 1.0000x reference)
#include <cuda_runtime.h>
#include <cuda_fp16.h>
#include <math.h>
#include <stdint.h>

// Problem dims
#define BATCH 4
#define TSEQ  1024
#define BT    4096
#define DMODEL 1024
#define NE    8
#define FF    4096
#define CAP   9216
#define NTILES 72

// ---------------- static device scratch ----------------
__device__ float g_x2 [BT * DMODEL];
__device__ float g_xn [BT * DMODEL];
__device__ float g_eo [CAP * DMODEL];
__device__ int   g_eidx[BT * 2];
__device__ float g_wts [BT * 2];
__device__ int   g_rows[BT * 2];
__device__ int   g_tile_e[NTILES];

// fp16 split scratch
__device__ __half g_aHi [BT * DMODEL];
__device__ __half g_aLo [BT * DMODEL];
__device__ __half g_qkvHi[BT * 3 * DMODEL];
__device__ __half g_qkvLo[BT * 3 * DMODEL];
__device__ __half g_wHi [NE * FF * DMODEL];
__device__ __half g_wLo [NE * FF * DMODEL];
__device__ __half g_xgHi[CAP * DMODEL];
__device__ __half g_xgLo[CAP * DMODEL];
__device__ __half g_hidHi[CAP * FF];
__device__ __half g_hidLo[CAP * FF];

__device__ __forceinline__ float gelu_f(float v) {
    return 0.5f * v * (1.0f + erff(v * 0.70710678118654752f));
}

// ---------------- PTX helpers ----------------
__device__ __forceinline__ uint32_t smem_u32(const void* p) {
    uint32_t a;
    asm("{ .reg .u64 t; cvta.to.shared.u64 t, %1; cvt.u32.u64 %0, t; }" : "=r"(a) : "l"(p));
    return a;
}
__device__ __forceinline__ void cpa16(uint32_t dst, const void* src) {
    asm volatile("cp.async.cg.shared.global [%0], [%1], 16;" :: "r"(dst), "l"(src));
}
__device__ __forceinline__ void cp_commit() { asm volatile("cp.async.commit_group;" ::: "memory"); }
template<int NPEND> __device__ __forceinline__ void cp_wait() {
    asm volatile("cp.async.wait_group %0;" :: "n"(NPEND) : "memory");
}
__device__ __forceinline__ void ldm_x4(uint32_t* r, uint32_t a) {
    asm volatile("ldmatrix.sync.aligned.m8n8.x4.shared.b16 {%0,%1,%2,%3}, [%4];"
        : "=r"(r[0]), "=r"(r[1]), "=r"(r[2]), "=r"(r[3]) : "r"(a));
}
__device__ __forceinline__ void ldm_x4t(uint32_t* r, uint32_t a) {
    asm volatile("ldmatrix.sync.aligned.m8n8.x4.trans.shared.b16 {%0,%1,%2,%3}, [%4];"
        : "=r"(r[0]), "=r"(r[1]), "=r"(r[2]), "=r"(r[3]) : "r"(a));
}
__device__ __forceinline__ void mma_f16(float* d, const uint32_t* a, const uint32_t* b) {
    asm volatile("mma.sync.aligned.m16n8k16.row.col.f32.f16.f16.f32 "
        "{%0,%1,%2,%3}, {%4,%5,%6,%7}, {%8,%9}, {%0,%1,%2,%3};"
        : "+f"(d[0]), "+f"(d[1]), "+f"(d[2]), "+f"(d[3])
        : "r"(a[0]), "r"(a[1]), "r"(a[2]), "r"(a[3]), "r"(b[0]), "r"(b[1]));
}
__device__ __forceinline__ uint32_t pack2h(float x, float y) {
    __half2 h = __halves2half2(__float2half(x), __float2half(y));
    return *(uint32_t*)&h;
}

// ---------------- HMMA NT GEMM ----------------
// TERMS=3: D = Ahi*Bhi + Ahi*Blo + Alo*Bhi  (NSTG=3, 4 mats/stage)
// TERMS=2: D = (Ahi+Alo)*B                  (NSTG=4, 3 mats/stage)
#define KCH  32
#define MATB  (128 * 64)
#define SWO(row_, chk_) ((uint32_t)((row_) * 64 + (((chk_) ^ (((row_) >> 1) & 3)) << 4)))

// EPI: 0 fp32; 1 fp32+Res; 2 gelu->hi/lo; 3 hi/lo
template<int EPI, int TERMS>
__global__ void __launch_bounds__(128, 2) hmma_gemm(
    const __half* __restrict__ Ahi, const __half* __restrict__ Alo,
    const __half* __restrict__ Bhi, const __half* __restrict__ Blo,
    size_t bstride, const int* __restrict__ tile_e,
    float* __restrict__ C, const float* __restrict__ Res,
    __half* __restrict__ Chi, __half* __restrict__ Clo,
    int N, int K)
{
    constexpr int NMAT = (TERMS == 3) ? 4 : 3;
    constexpr int NSTG_T = (TERMS == 3) ? 3 : 4;
    constexpr uint32_t STGB = NMAT * MATB;
    extern __shared__ char smem[];
    uint32_t sbase = smem_u32(smem);
    int by = blockIdx.y, bx = blockIdx.x;

    const __half* Bh = Bhi;
    const __half* Bl = Blo;
    if (tile_e) {
        int e = tile_e[by];
        if (e < 0) return;
        Bh += (size_t)e * bstride;
        if (TERMS == 3) Bl += (size_t)e * bstride;
    }

    int tid = threadIdx.x, wid = tid >> 5, lane = tid & 31;
    int warpM = (wid >> 1) * 64, warpN = (wid & 1) * 64;

    int lrow = tid >> 2;
    int lchk = tid & 3;
    const __half* pAh = Ahi + (size_t)(by * 128 + lrow) * K + lchk * 8;
    const __half* pAl = Alo + (size_t)(by * 128 + lrow) * K + lchk * 8;
    const __half* pB0 = Bh + (size_t)(bx * 128 + lrow) * K + lchk * 8;
    const __half* pB1 = (TERMS == 3) ? (Bl + (size_t)(bx * 128 + lrow) * K + lchk * 8) : nullptr;
    uint32_t so = SWO(lrow, lchk);

#define LOADST(s_) do { \
        uint32_t sb_ = sbase + ((s_) % NSTG_T) * STGB; \
        size_t ko_ = (size_t)(s_) * KCH; \
        _Pragma("unroll") \
        for (int p_ = 0; p_ < 4; p_++) { \
            uint32_t o_ = so + p_ * (32 * 64); \
            size_t g_ = ko_ + (size_t)p_ * 32 * K; \
            cpa16(sb_ + o_,            pAh + g_); \
            cpa16(sb_ + MATB + o_,     pAl + g_); \
            cpa16(sb_ + 2 * MATB + o_, pB0 + g_); \
            if (TERMS == 3) cpa16(sb_ + 3 * MATB + o_, pB1 + g_); \
        } \
        cp_commit(); \
    } while (0)

    float acc[4][8][4];
#pragma unroll
    for (int i = 0; i < 4; i++)
#pragma unroll
        for (int j = 0; j < 8; j++)
#pragma unroll
            for (int q = 0; q < 4; q++) acc[i][j][q] = 0.f;

    int S = K / KCH;
    LOADST(0);
    LOADST(1);
    if (NSTG_T == 4) LOADST(2);

    int a_r = lane & 15;
    int a_c = lane >> 4;
    int b_r = ((lane >> 3) & 1) * 8 + (lane & 7);
    int b_c = lane >> 4;

    for (int s = 0; s < S; s++) {
        if (NSTG_T == 4) {
            if (s + 2 <= S - 1) cp_wait<2>();
            else if (s + 1 <= S - 1) cp_wait<1>();
            else cp_wait<0>();
        } else {
            if (s + 1 <= S - 1) cp_wait<1>();
            else cp_wait<0>();
        }
        __syncthreads();
        if (s + NSTG_T - 1 < S) LOADST(s + NSTG_T - 1);

        uint32_t sa = sbase + (s % NSTG_T) * STGB;
#pragma unroll
        for (int ks = 0; ks < 2; ks++) {
            uint32_t ah[4][4], al[4][4], bhf[8][2];
#pragma unroll
            for (int i = 0; i < 4; i++) {
                int row = warpM + 16 * i + a_r;
                uint32_t ad = sa + SWO(row, ks * 2 + a_c);
                ldm_x4(ah[i], ad);
                ldm_x4(al[i], ad + MATB);
            }
#pragma unroll
            for (int jj = 0; jj < 4; jj++) {
                int row = warpN + 16 * jj + b_r;
                uint32_t bd = sa + 2 * MATB + SWO(row, ks * 2 + b_c);
                uint32_t q[4];
                ldm_x4(q, bd);
                bhf[2 * jj][0] = q[0]; bhf[2 * jj][1] = q[2];
                bhf[2 * jj + 1][0] = q[1]; bhf[2 * jj + 1][1] = q[3];
            }
#pragma unroll
            for (int i = 0; i < 4; i++)
#pragma unroll
                for (int j = 0; j < 8; j++)
                    mma_f16(acc[i][j], ah[i], bhf[j]);
#pragma unroll
            for (int i = 0; i < 4; i++)
#pragma unroll
                for (int j = 0; j < 8; j++)
                    mma_f16(acc[i][j], al[i], bhf[j]);
            if (TERMS == 3) {
                uint32_t blf[8][2];
#pragma unroll
                for (int jj = 0; jj < 4; jj++) {
                    int row = warpN + 16 * jj + b_r;
                    uint32_t bd = sa + 3 * MATB + SWO(row, ks * 2 + b_c);
                    uint32_t p[4];
                    ldm_x4(p, bd);
                    blf[2 * jj][0] = p[0]; blf[2 * jj][1] = p[2];
                    blf[2 * jj + 1][0] = p[1]; blf[2 * jj + 1][1] = p[3];
                }
#pragma unroll
                for (int i = 0; i < 4; i++)
#pragma unroll
                    for (int j = 0; j < 8; j++)
                        mma_f16(acc[i][j], ah[i], blf[j]);
            }
        }
    }
#undef LOADST

    int r0 = lane >> 2, c0 = (lane & 3) * 2;
#pragma unroll
    for (int i = 0; i < 4; i++) {
#pragma unroll
        for (int j = 0; j < 8; j++) {
            int row = by * 128 + warpM + 16 * i + r0;
            int col = bx * 128 + warpN + 8 * j + c0;
#pragma unroll
            for (int half = 0; half < 2; half++) {
                size_t off = (size_t)(row + half * 8) * N + col;
                float v0 = acc[i][j][2 * half];
                float v1 = acc[i][j][2 * half + 1];
                if (EPI == 0) {
                    *(float2*)(C + off) = make_float2(v0, v1);
                } else if (EPI == 1) {
                    float2 rr = *(const float2*)(Res + off);
                    *(float2*)(C + off) = make_float2(v0 + rr.x, v1 + rr.y);
                } else {
                    if (EPI == 2) { v0 = gelu_f(v0); v1 = gelu_f(v1); }
                    __half h0 = __float2half(v0);
                    __half h1 = __float2half(v1);
                    __half l0 = __float2half(v0 - __half2float(h0));
                    __half l1 = __float2half(v1 - __half2float(h1));
                    *(__half2*)(Chi + off) = __halves2half2(h0, h1);
                    *(__half2*)(Clo + off) = __halves2half2(l0, l1);
                }
            }
        }
    }
}

// ---------------- HMMA flash attention, double-buffered K/V ----------------
#define SWO8(row_, chk_) ((uint32_t)((row_) * 128 + (((chk_) ^ ((row_) & 7)) << 4)))
#define AT_Q    0
#define AT_QL   8192
#define AT_KV   16384              // 2 slots x 32768 (K, KL, V, VL @ 8192 each)
#define AT_SLOT 32768
#define AT_SMEM (16384 + 2 * 32768)   // 81920 -> 2 CTAs/SM

__global__ void __launch_bounds__(128) attn_hmma(
    const __half* __restrict__ qkvHi, const __half* __restrict__ qkvLo,
    __half* __restrict__ oHi, __half* __restrict__ oLo)
{
    extern __shared__ char smem[];
    uint32_t sbase = smem_u32(smem);
    int qi = blockIdx.x;
    int bh = blockIdx.y;
    int b = bh >> 4, h = bh & 15;
    int tid = threadIdx.x, wid = tid >> 5, lane = tid & 31;
    int warpM = wid * 16;

    const size_t tokbase = (size_t)b * TSEQ * 3072;
    const __half* qH = qkvHi + tokbase + h * 64;
    const __half* qL = qkvLo + tokbase + h * 64;
    const __half* kH = qH + 1024;
    const __half* kL = qL + 1024;
    const __half* vH = qH + 2048;
    const __half* vL = qL + 2048;

    int lrow = tid >> 1;
    int lc0 = (tid & 1) * 4;

    // Q tiles (one commit group)
#pragma unroll
    for (int i = 0; i < 4; i++) {
        int chk = lc0 + i;
        size_t g = (size_t)(qi * 64 + lrow) * 3072 + chk * 8;
        cpa16(sbase + AT_Q + SWO8(lrow, chk), qH + g);
        cpa16(sbase + AT_QL + SWO8(lrow, chk), qL + g);
    }
    cp_commit();

#define LOADKV(jt_) do { \
        uint32_t slot_ = sbase + AT_KV + ((jt_) & 1) * AT_SLOT; \
        _Pragma("unroll") \
        for (int i_ = 0; i_ < 4; i_++) { \
            int chk_ = lc0 + i_; \
            size_t g_ = (size_t)((jt_) * 64 + lrow) * 3072 + chk_ * 8; \
            uint32_t soff_ = SWO8(lrow, chk_); \
            cpa16(slot_ + soff_,         kH + g_); \
            cpa16(slot_ + 8192 + soff_,  kL + g_); \
            cpa16(slot_ + 16384 + soff_, vH + g_); \
            cpa16(slot_ + 24576 + soff_, vL + g_); \
        } \
        cp_commit(); \
    } while (0)

    LOADKV(0);

    float acc_o[8][4];
#pragma unroll
    for (int j = 0; j < 8; j++)
#pragma unroll
        for (int q = 0; q < 4; q++) acc_o[j][q] = 0.f;
    float mrow[2] = {-1e30f, -1e30f};
    float lrw[2] = {0.f, 0.f};

    int a_r = lane & 15;
    int a_c = lane >> 4;
    int b_r = ((lane >> 3) & 1) * 8 + (lane & 7);
    int b_c = lane >> 4;

    for (int jt = 0; jt <= qi; jt++) {
        __syncthreads();   // all warps finished reading slot (jt+1)&1 (used at jt-1)
        if (jt + 1 <= qi) { LOADKV(jt + 1); cp_wait<1>(); }
        else cp_wait<0>();
        __syncthreads();

        uint32_t slot = sbase + AT_KV + (jt & 1) * AT_SLOT;

        float s[8][4];
#pragma unroll
        for (int j = 0; j < 8; j++)
#pragma unroll
            for (int q = 0; q < 4; q++) s[j][q] = 0.f;

#pragma unroll
        for (int kc = 0; kc < 4; kc++) {
            uint32_t ah[4], al[4], kf[8][2];
            uint32_t ad = sbase + AT_Q + SWO8(warpM + a_r, kc * 2 + a_c);
            ldm_x4(ah, ad);
            ldm_x4(al, ad + (AT_QL - AT_Q));
#pragma unroll
            for (int jj = 0; jj < 4; jj++) {
                uint32_t bd = slot + SWO8(16 * jj + b_r, kc * 2 + b_c);
                uint32_t q[4];
                ldm_x4(q, bd);
                kf[2 * jj][0] = q[0]; kf[2 * jj][1] = q[2];
                kf[2 * jj + 1][0] = q[1]; kf[2 * jj + 1][1] = q[3];
            }
#pragma unroll
            for (int j = 0; j < 8; j++)
                mma_f16(s[j], ah, kf[j]);
#pragma unroll
            for (int j = 0; j < 8; j++)
                mma_f16(s[j], al, kf[j]);
            uint32_t klf[8][2];
#pragma unroll
            for (int jj = 0; jj < 4; jj++) {
                uint32_t bd = slot + 8192 + SWO8(16 * jj + b_r, kc * 2 + b_c);
                uint32_t p[4];
                ldm_x4(p, bd);
                klf[2 * jj][0] = p[0]; klf[2 * jj][1] = p[2];
                klf[2 * jj + 1][0] = p[1]; klf[2 * jj + 1][1] = p[3];
            }
#pragma unroll
            for (int j = 0; j < 8; j++)
                mma_f16(s[j], ah, klf[j]);
        }

        int rA = qi * 64 + warpM + (lane >> 2);
        int cbase = jt * 64 + (lane & 3) * 2;
#pragma unroll
        for (int j = 0; j < 8; j++) {
#pragma unroll
            for (int q = 0; q < 4; q++) {
                float v = s[j][q] * 0.125f;
                if (jt == qi) {
                    int col = cbase + j * 8 + (q & 1);
                    int row = rA + (q >= 2 ? 8 : 0);
                    if (col > row) v = -1e30f;
                }
                s[j][q] = v;
            }
        }

#pragma unroll
        for (int hf = 0; hf < 2; hf++) {
            float mt = -1e30f;
#pragma unroll
            for (int j = 0; j < 8; j++)
                mt = fmaxf(mt, fmaxf(s[j][2 * hf], s[j][2 * hf + 1]));
            mt = fmaxf(mt, __shfl_xor_sync(0xffffffffu, mt, 1));
            mt = fmaxf(mt, __shfl_xor_sync(0xffffffffu, mt, 2));
            float mn = fmaxf(mrow[hf], mt);
            float alpha = __expf(mrow[hf] - mn);
            float ls = 0.f;
#pragma unroll
            for (int j = 0; j < 8; j++) {
                float p0 = __expf(s[j][2 * hf] - mn);
                float p1 = __expf(s[j][2 * hf + 1] - mn);
                s[j][2 * hf] = p0; s[j][2 * hf + 1] = p1;
                ls += p0 + p1;
            }
            ls += __shfl_xor_sync(0xffffffffu, ls, 1);
            ls += __shfl_xor_sync(0xffffffffu, ls, 2);
            lrw[hf] = lrw[hf] * alpha + ls;
            mrow[hf] = mn;
#pragma unroll
            for (int j = 0; j < 8; j++) {
                acc_o[j][2 * hf] *= alpha;
                acc_o[j][2 * hf + 1] *= alpha;
            }
        }

#pragma unroll
        for (int kc = 0; kc < 4; kc++) {
            uint32_t phi[4], plo[4];
            {
                float p00 = s[2 * kc][0], p01 = s[2 * kc][1];
                float p02 = s[2 * kc][2], p03 = s[2 * kc][3];
                float p10 = s[2 * kc + 1][0], p11 = s[2 * kc + 1][1];
                float p12 = s[2 * kc + 1][2], p13 = s[2 * kc + 1][3];
                phi[0] = pack2h(p00, p01);
                phi[1] = pack2h(p02, p03);
                phi[2] = pack2h(p10, p11);
                phi[3] = pack2h(p12, p13);
                __half2 h0 = *(__half2*)&phi[0];
                __half2 h1 = *(__half2*)&phi[1];
                __half2 h2 = *(__half2*)&phi[2];
                __half2 h3 = *(__half2*)&phi[3];
                plo[0] = pack2h(p00 - __half2float(__low2half(h0)), p01 - __half2float(__high2half(h0)));
                plo[1] = pack2h(p02 - __half2float(__low2half(h1)), p03 - __half2float(__high2half(h1)));
                plo[2] = pack2h(p10 - __half2float(__low2half(h2)), p11 - __half2float(__high2half(h2)));
                plo[3] = pack2h(p12 - __half2float(__low2half(h3)), p13 - __half2float(__high2half(h3)));
            }
            uint32_t vfh[8][2], vfl[8][2];
#pragma unroll
            for (int g = 0; g < 4; g++) {
                uint32_t bd = slot + 16384 + SWO8(kc * 16 + b_r, 2 * g + b_c);
                uint32_t q[4];
                ldm_x4t(q, bd);
                vfh[2 * g][0] = q[0]; vfh[2 * g][1] = q[1];
                vfh[2 * g + 1][0] = q[2]; vfh[2 * g + 1][1] = q[3];
                uint32_t p[4];
                ldm_x4t(p, bd + 8192);
                vfl[2 * g][0] = p[0]; vfl[2 * g][1] = p[1];
                vfl[2 * g + 1][0] = p[2]; vfl[2 * g + 1][1] = p[3];
            }
#pragma unroll
            for (int j = 0; j < 8; j++)
                mma_f16(acc_o[j], phi, vfh[j]);
#pragma unroll
            for (int j = 0; j < 8; j++)
                mma_f16(acc_o[j], phi, vfl[j]);
#pragma unroll
            for (int j = 0; j < 8; j++)
                mma_f16(acc_o[j], plo, vfh[j]);
        }
    }
#undef LOADKV

    float inv0 = 1.0f / lrw[0];
    float inv1 = 1.0f / lrw[1];
#pragma unroll
    for (int j = 0; j < 8; j++) {
#pragma unroll
        for (int hf = 0; hf < 2; hf++) {
            int row = b * TSEQ + qi * 64 + warpM + (lane >> 2) + hf * 8;
            int col = h * 64 + j * 8 + (lane & 3) * 2;
            float inv = hf ? inv1 : inv0;
            float v0 = acc_o[j][2 * hf] * inv;
            float v1 = acc_o[j][2 * hf + 1] * inv;
            __half h0 = __float2half(v0);
            __half h1 = __float2half(v1);
            __half l0 = __float2half(v0 - __half2float(h0));
            __half l1 = __float2half(v1 - __half2float(h1));
            size_t off = (size_t)row * DMODEL + col;
            *(__half2*)(oHi + off) = __halves2half2(h0, h1);
            *(__half2*)(oLo + off) = __halves2half2(l0, l1);
        }
    }
}

// ---------------- fp32 -> fp16 hi/lo split ----------------
__global__ __launch_bounds__(256) void split2_kernel(const float* __restrict__ x,
                                                     __half* __restrict__ hi,
                                                     __half* __restrict__ lo, int n4) {
    int i = blockIdx.x * 256 + threadIdx.x;
    if (i >= n4) return;
    float4 v = ((const float4*)x)[i];
    __half h0 = __float2half(v.x), h1 = __float2half(v.y);
    __half h2 = __float2half(v.z), h3 = __float2half(v.w);
    __half l0 = __float2half(v.x - __half2float(h0));
    __half l1 = __float2half(v.y - __half2float(h1));
    __half l2 = __float2half(v.z - __half2float(h2));
    __half l3 = __float2half(v.w - __half2float(h3));
    ((__half2*)hi)[2 * i]     = __halves2half2(h0, h1);
    ((__half2*)hi)[2 * i + 1] = __halves2half2(h2, h3);
    ((__half2*)lo)[2 * i]     = __halves2half2(l0, l1);
    ((__half2*)lo)[2 * i + 1] = __halves2half2(l2, l3);
}

// ---------------- fp32 -> fp16 single (post-router weights) ----------------
__global__ __launch_bounds__(256) void cvt_kernel(const float* __restrict__ x,
                                                  __half* __restrict__ y, int n4) {
    int i = blockIdx.x * 256 + threadIdx.x;
    if (i >= n4) return;
    float4 v = ((const float4*)x)[i];
    ((__half2*)y)[2 * i]     = __floats2half2_rn(v.x, v.y);
    ((__half2*)y)[2 * i + 1] = __floats2half2_rn(v.z, v.w);
}

// ---------------- LayerNorm fused with hi/lo split ----------------
template<int MODE>
__global__ __launch_bounds__(256) void ln_fused(const float* __restrict__ x,
                                                const float* __restrict__ w,
                                                const float* __restrict__ c,
                                                float* __restrict__ outf,
                                                __half* __restrict__ hi,
                                                __half* __restrict__ lo) {
    int row = blockIdx.x;
    int tid = threadIdx.x;
    const float* xr = x + (size_t)row * DMODEL;
    float4 v = *(const float4*)(xr + tid * 4);

    __shared__ float red[8];
    __shared__ float tot;

    float s = v.x + v.y + v.z + v.w;
#pragma unroll
    for (int m = 16; m > 0; m >>= 1) s += __shfl_xor_sync(0xffffffffu, s, m);
    if ((tid & 31) == 0) red[tid >> 5] = s;
    __syncthreads();
    if (tid == 0) { float t = 0.f; for (int i = 0; i < 8; i++) t += red[i]; tot = t; }
    __syncthreads();
    float mean = tot * (1.0f / DMODEL);
    float dx = v.x - mean, dy = v.y - mean, dz = v.z - mean, dw = v.w - mean;
    float s2 = dx * dx + dy * dy + dz * dz + dw * dw;
    __syncthreads();
#pragma unroll
    for (int m = 16; m > 0; m >>= 1) s2 += __shfl_xor_sync(0xffffffffu, s2, m);
    if ((tid & 31) == 0) red[tid >> 5] = s2;
    __syncthreads();
    if (tid == 0) { float t = 0.f; for (int i = 0; i < 8; i++) t += red[i]; tot = t; }
    __syncthreads();
    float inv = rsqrtf(tot * (1.0f / DMODEL) + 1e-5f);

    int d0 = tid * 4;
    float4 w4 = *(const float4*)(w + d0);
    float r0 = dx * inv * w4.x;
    float r1 = dy * inv * w4.y;
    float r2 = dz * inv * w4.z;
    float r3 = dw * inv * w4.w;
    if (MODE == 0) {
        int b = row >> 10;
        float4 c4 = *(const float4*)(c + (size_t)b * DMODEL + d0);
        r0 += c4.x; r1 += c4.y; r2 += c4.z; r3 += c4.w;
    }
    if (MODE == 1)
        *(float4*)(outf + (size_t)row * DMODEL + d0) = make_float4(r0, r1, r2, r3);
    __half h0 = __float2half(r0), h1 = __float2half(r1);
    __half h2 = __float2half(r2), h3 = __float2half(r3);
    __half l0 = __float2half(r0 - __half2float(h0));
    __half l1 = __float2half(r1 - __half2float(h1));
    __half l2 = __float2half(r2 - __half2float(h2));
    __half l3 = __float2half(r3 - __half2float(h3));
    size_t ho = (size_t)row * DMODEL + d0;
    *(__half2*)(hi + ho)     = __halves2half2(h0, h1);
    *(__half2*)(hi + ho + 2) = __halves2half2(h2, h3);
    *(__half2*)(lo + ho)     = __halves2half2(l0, l1);
    *(__half2*)(lo + ho + 2) = __halves2half2(l2, l3);
}

// ---------------- router ----------------
__global__ __launch_bounds__(256) void router_kernel(const float* __restrict__ xn,
                                                     const float* __restrict__ rw,
                                                     int* __restrict__ eidx,
                                                     float* __restrict__ wts) {
    int t = blockIdx.x;
    int tid = threadIdx.x, lane = tid & 31, wp = tid >> 5;
    const float* xr = xn + (size_t)t * DMODEL;
    const float* wr = rw + (size_t)wp * DMODEL;
    float s = 0.f;
    for (int d = lane * 4; d < DMODEL; d += 128) {
        float4 a = *(const float4*)(xr + d);
        float4 b = *(const float4*)(wr + d);
        s += a.x * b.x + a.y * b.y + a.z * b.z + a.w * b.w;
    }
#pragma unroll
    for (int mm = 16; mm > 0; mm >>= 1) s += __shfl_xor_sync(0xffffffffu, s, mm);
    __shared__ float lg[8];
    if (lane == 0) lg[wp] = s;
    __syncthreads();
    if (tid == 0) {
        float mx = lg[0];
        for (int e = 1; e < NE; e++) mx = fmaxf(mx, lg[e]);
        float p[NE]; float sum = 0.f;
        for (int e = 0; e < NE; e++) { p[e] = expf(lg[e] - mx); sum += p[e]; }
        float inv = 1.0f / sum;
        for (int e = 0; e < NE; e++) {
            float v = p[e] * inv + 1e-9f;
            p[e] = fminf(fmaxf(v, 1e-9f), 1.0f - 1e-9f);
        }
        int i0 = 0;
        for (int e = 1; e < NE; e++) if (p[e] > p[i0]) i0 = e;
        int i1 = (i0 == 0) ? 1 : 0;
        for (int e = 0; e < NE; e++) if (e != i0 && p[e] > p[i1]) i1 = e;
        float d2 = 1.0f / (p[i0] + p[i1]);
        eidx[2 * t] = i0; eidx[2 * t + 1] = i1;
        wts[2 * t] = p[i0] * d2; wts[2 * t + 1] = p[i1] * d2;
    }
}

// ---------------- build per-expert CSR ----------------
__global__ __launch_bounds__(256) void build_kernel(const int* __restrict__ eidx,
                                                    int* __restrict__ rows,
                                                    int* __restrict__ tile_e) {
    __shared__ int cnt[NE];
    __shared__ int off[NE];
    int tid = threadIdx.x;
    if (tid < NE) cnt[tid] = 0;
    __syncthreads();
    for (int a = tid; a < BT * 2; a += 256) atomicAdd(&cnt[eidx[a]], 1);
    __syncthreads();
    if (tid == 0) {
        int o = 0;
        for (int e = 0; e < NE; e++) { off[e] = o; o = (o + cnt[e] + 127) & ~127; }
        for (int tt = 0; tt < NTILES; tt++) tile_e[tt] = -1;
        for (int e = 0; e < NE; e++) {
            int nt = (cnt[e] + 127) >> 7;
            int t0 = off[e] >> 7;
            for (int i = 0; i < nt; i++) tile_e[t0 + i] = e;
        }
    }
    __syncthreads();
    if (tid < NE) cnt[tid] = 0;
    __syncthreads();
    for (int a = tid; a < BT * 2; a += 256) {
        int e = eidx[a];
        int pos = atomicAdd(&cnt[e], 1);
        rows[a] = off[e] + pos;
    }
}

// ---------------- gather fp16 rows ----------------
__global__ __launch_bounds__(128) void gather_hf(const __half* __restrict__ xhi,
                                                 const __half* __restrict__ xlo,
                                                 const int* __restrict__ rows,
                                                 __half* __restrict__ ghi,
                                                 __half* __restrict__ glo) {
    int a = blockIdx.x;
    int r = rows[a];
    int t = a >> 1;
    int tid = threadIdx.x;
    ((uint4*)(ghi + (size_t)r * DMODEL))[tid] = ((const uint4*)(xhi + (size_t)t * DMODEL))[tid];
    ((uint4*)(glo + (size_t)r * DMODEL))[tid] = ((const uint4*)(xlo + (size_t)t * DMODEL))[tid];
}

// ---------------- combine ----------------
__global__ __launch_bounds__(256) void combine_kernel(const float* __restrict__ xn,
                                                      const float* __restrict__ eo,
                                                      const int* __restrict__ rows,
                                                      const float* __restrict__ wts,
                                                      float* __restrict__ out) {
    int t = blockIdx.x;
    int r0 = rows[2 * t], r1 = rows[2 * t + 1];
    float w0 = wts[2 * t], w1 = wts[2 * t + 1];
    int tid = threadIdx.x;
    float4 a = *(const float4*)(xn + (size_t)t * DMODEL + tid * 4);
    float4 b = *(const float4*)(eo + (size_t)r0 * DMODEL + tid * 4);
    float4 c = *(const float4*)(eo + (size_t)r1 * DMODEL + tid * 4);
    float4 r;
    r.x = a.x + w0 * b.x + w1 * c.x;
    r.y = a.y + w0 * b.y + w1 * c.y;
    r.z = a.z + w0 * b.z + w1 * c.z;
    r.w = a.w + w0 * b.w + w1 * c.w;
    *(float4*)(out + (size_t)t * DMODEL + tid * 4) = r;
}

// ---------------- host launcher ----------------
extern "C" void kernel_launch(void* const* d_in, const int* in_sizes, int n_in,
                              void* d_out, int out_size) {
    const float* x        = (const float*)d_in[0];
    const float* c        = (const float*)d_in[1];
    const float* ln1_w    = (const float*)d_in[2];
    const float* w_qkv    = (const float*)d_in[3];
    const float* w_proj   = (const float*)d_in[4];
    const float* ln2_w    = (const float*)d_in[5];
    const float* router_w = (const float*)d_in[6];
    const float* ew1      = (const float*)d_in[7];
    const float* ew2      = (const float*)d_in[8];
    float* out = (float*)d_out;

    float *p_x2, *p_xn, *p_eo, *p_wts;
    int *p_eidx, *p_rows, *p_te;
    __half *p_aHi, *p_aLo, *p_qkvHi, *p_qkvLo, *p_wHi, *p_wLo;
    __half *p_xgHi, *p_xgLo, *p_hidHi, *p_hidLo;
    cudaGetSymbolAddress((void**)&p_x2,    g_x2);
    cudaGetSymbolAddress((void**)&p_xn,    g_xn);
    cudaGetSymbolAddress((void**)&p_eo,    g_eo);
    cudaGetSymbolAddress((void**)&p_wts,   g_wts);
    cudaGetSymbolAddress((void**)&p_eidx,  g_eidx);
    cudaGetSymbolAddress((void**)&p_rows,  g_rows);
    cudaGetSymbolAddress((void**)&p_te,    g_tile_e);
    cudaGetSymbolAddress((void**)&p_aHi,   g_aHi);
    cudaGetSymbolAddress((void**)&p_aLo,   g_aLo);
    cudaGetSymbolAddress((void**)&p_qkvHi, g_qkvHi);
    cudaGetSymbolAddress((void**)&p_qkvLo, g_qkvLo);
    cudaGetSymbolAddress((void**)&p_wHi,   g_wHi);
    cudaGetSymbolAddress((void**)&p_wLo,   g_wLo);
    cudaGetSymbolAddress((void**)&p_xgHi,  g_xgHi);
    cudaGetSymbolAddress((void**)&p_xgLo,  g_xgLo);
    cudaGetSymbolAddress((void**)&p_hidHi, g_hidHi);
    cudaGetSymbolAddress((void**)&p_hidLo, g_hidLo);

    const int SMEM3 = 3 * 4 * MATB;   // 98304, NSTG=3 x 4 mats
    const int SMEM2 = 4 * 3 * MATB;   // 98304, NSTG=4 x 3 mats
    cudaFuncSetAttribute((const void*)hmma_gemm<1, 3>, cudaFuncAttributeMaxDynamicSharedMemorySize, SMEM3);
    cudaFuncSetAttribute((const void*)hmma_gemm<3, 3>, cudaFuncAttributeMaxDynamicSharedMemorySize, SMEM3);
    cudaFuncSetAttribute((const void*)hmma_gemm<2, 2>, cudaFuncAttributeMaxDynamicSharedMemorySize, SMEM2);
    cudaFuncSetAttribute((const void*)hmma_gemm<0, 2>, cudaFuncAttributeMaxDynamicSharedMemorySize, SMEM2);
    cudaFuncSetAttribute(attn_hmma, cudaFuncAttributeMaxDynamicSharedMemorySize, AT_SMEM);

    // 1) h = LN1(x)*w + c -> fp16 hi/lo directly
    ln_fused<0><<<BT, 256>>>(x, ln1_w, c, nullptr, p_aHi, p_aLo);
    split2_kernel<<<(3 * DMODEL * DMODEL / 4 + 255) / 256, 256>>>(w_qkv, p_wHi, p_wLo, 3 * DMODEL * DMODEL / 4);

    // 2) qkv = h @ w_qkv^T -> fp16 hi/lo  (3-term)
    hmma_gemm<3, 3><<<dim3(24, 32), 128, SMEM3>>>(p_aHi, p_aLo, p_wHi, p_wLo, 0, nullptr,
                                                  nullptr, nullptr, p_qkvHi, p_qkvLo, 3072, 1024);

    // 3) causal attention (HMMA, 3-term, double-buffered KV)
    attn_hmma<<<dim3(16, 64), 128, AT_SMEM>>>(p_qkvHi, p_qkvLo, p_aHi, p_aLo);

    // 4) x2 = x + o @ w_proj^T  (3-term)
    split2_kernel<<<(DMODEL * DMODEL / 4 + 255) / 256, 256>>>(w_proj, p_wHi, p_wLo, DMODEL * DMODEL / 4);
    hmma_gemm<1, 3><<<dim3(8, 32), 128, SMEM3>>>(p_aHi, p_aLo, p_wHi, p_wLo, 0, nullptr,
                                                 p_x2, x, nullptr, nullptr, 1024, 1024);

    // 5) xn = LN2(x2) -> fp32 + fp16 hi/lo
    ln_fused<1><<<BT, 256>>>(p_x2, ln2_w, nullptr, p_xn, p_aHi, p_aLo);

    // 6) router + CSR (fp32: routing exact)
    router_kernel<<<BT, 256>>>(p_xn, router_w, p_eidx, p_wts);
    build_kernel<<<1, 256>>>(p_eidx, p_rows, p_te);

    // 7) gather fp16
    gather_hf<<<BT * 2, 128>>>(p_aHi, p_aLo, p_rows, p_xgHi, p_xgLo);

    // 8) hid = gelu(xg @ w1[e]^T)  (2-term, NSTG=4)
    cvt_kernel<<<(NE * FF * DMODEL / 4 + 255) / 256, 256>>>(ew1, p_wHi, NE * FF * DMODEL / 4);
    hmma_gemm<2, 2><<<dim3(32, NTILES), 128, SMEM2>>>(p_xgHi, p_xgLo, p_wHi, nullptr,
                                                      (size_t)FF * DMODEL, p_te,
                                                      nullptr, nullptr, p_hidHi, p_hidLo, FF, 1024);

    // 9) eo = hid @ w2[e]^T  (2-term, NSTG=4)
    cvt_kernel<<<(NE * DMODEL * FF / 4 + 255) / 256, 256>>>(ew2, p_wHi, NE * DMODEL * FF / 4);
    hmma_gemm<0, 2><<<dim3(8, NTILES), 128, SMEM2>>>(p_hidHi, p_hidLo, p_wHi, nullptr,
                                                     (size_t)DMODEL * FF, p_te,
                                                     p_eo, nullptr, nullptr, nullptr, 1024, 4096);

    // 10) out = xn + sum_k w_k * eo
    combine_kernel<<<BT, 256>>>(p_xn, p_eo, p_rows, p_wts, out);
}